// round 10
// baseline (speedup 1.0000x reference)
#include <cuda_runtime.h>

#define T_FRAMES 60
#define HID 32
#define NG 128          // 4*HID gate rows
#define EPSF 1e-5f
#define FULLM 0xffffffffu
#define LEAD 16         // frames staged before the loop starts
#define CONFIRM_T 12    // step at which we confirm all frames are done

// per-frame gate pre-activations (i/f/o rows pre-scaled by 0.5; g rows raw)
__device__ float g_gx[T_FRAMES * NG];
__device__ int   g_flag[T_FRAMES];
__device__ int   g_done = 0;

__device__ __forceinline__ float tanha(float x) {
    float r; asm("tanh.approx.f32 %0, %1;" : "=f"(r) : "f"(x)); return r;
}
__device__ __forceinline__ int ld_acquire_gpu(const int* p) {
    int v; asm volatile("ld.acquire.gpu.global.b32 %0, [%1];" : "=r"(v) : "l"(p)); return v;
}

// ---------------------------------------------------------------------------
// Fused kernel: blocks 0..59 = per-frame MLP+LN+W_ih matvec (parallel),
// block 60 = recurrence + output head.
// ---------------------------------------------------------------------------
__global__ void __launch_bounds__(128, 1) fused_kernel(
    const float* __restrict__ x,
    const float* __restrict__ w00, const float* __restrict__ b00,
    const float* __restrict__ w01, const float* __restrict__ b01,
    const float* __restrict__ lng, const float* __restrict__ lnb,
    const float* __restrict__ wih, const float* __restrict__ bih,
    const float* __restrict__ bhh,
    const float* __restrict__ whh,
    const float* __restrict__ bng, const float* __restrict__ bnb,
    const float* __restrict__ w10, const float* __restrict__ b10,
    const float* __restrict__ w11, const float* __restrict__ b11,
    const float* __restrict__ w12, const float* __restrict__ b12,
    float* __restrict__ out)
{
    const int tid  = threadIdx.x;
    const int wid  = tid >> 5;
    const int lane = tid & 31;

    if (blockIdx.x < T_FRAMES) {
        // =================== frame path (parallel over t) ===================
        const int t = blockIdx.x;

        __shared__ float sx[63];
        __shared__ float sf1[63];
        __shared__ float sf2[64];
        __shared__ float sfn[64];
        __shared__ float s_mu, s_rstd;

        if (tid < 63) sx[tid] = x[t * 63 + tid];
        __syncthreads();

        if (tid < 63) {
            float acc = b00[tid];
            const float* wr = w00 + tid * 63;
            #pragma unroll
            for (int k = 0; k < 63; k++) acc = fmaf(wr[k], sx[k], acc);
            sf1[tid] = fmaxf(acc, 0.0f);
        }
        __syncthreads();

        if (tid < 64) {
            float acc = b01[tid];
            const float* wr = w01 + tid * 63;
            #pragma unroll
            for (int k = 0; k < 63; k++) acc = fmaf(wr[k], sf1[k], acc);
            sf2[tid] = fmaxf(acc, 0.0f);
        }
        __syncthreads();

        if (tid < 32) {
            float v0 = sf2[tid], v1 = sf2[tid + 32];
            float s = v0 + v1;
            float q = v0 * v0 + v1 * v1;
            #pragma unroll
            for (int o = 16; o > 0; o >>= 1) {
                s += __shfl_xor_sync(FULLM, s, o);
                q += __shfl_xor_sync(FULLM, q, o);
            }
            if (tid == 0) {
                float mu  = s * (1.0f / 64.0f);
                float var = q * (1.0f / 64.0f) - mu * mu;
                s_mu   = mu;
                s_rstd = rsqrtf(var + EPSF);
            }
        }
        __syncthreads();

        if (tid < 64)
            sfn[tid] = (sf2[tid] - s_mu) * s_rstd * lng[tid] + lnb[tid];
        __syncthreads();

        {
            float acc = bih[tid] + bhh[tid];
            const float* wr = wih + tid * 64;
            #pragma unroll
            for (int k = 0; k < 64; k++) acc = fmaf(wr[k], sfn[k], acc);
            // g gate rows (64..95) raw; i/f/o rows scaled by 0.5 (sigmoid arg)
            float scale = ((tid >> 5) == 2) ? 1.0f : 0.5f;
            g_gx[t * NG + tid] = acc * scale;
        }
        __syncthreads();
        if (tid == 0) {
            __threadfence();
            atomicExch(&g_flag[t], 1);
            atomicAdd(&g_done, 1);
        }
        return;
    }

    // ======================= sequential path (block 60) =====================
    // lane mapping: element e = 8*wid + (lane>>2), gate g = lane&3,
    // gate row r = 32*g + e  (rows: i 0-31, f 32-63, g 64-95, o 96-127).
    __shared__ float sgx[T_FRAMES * NG];              // 30 KB staged gx
    __shared__ __align__(16) float sgate[2][NG];      // [elem*4 + gate]
    __shared__ __align__(16) float shbuf[4][HID];     // per-warp private h copy

    const int g   = lane & 3;
    const int e   = 8 * wid + (lane >> 2);
    const int row = 32 * g + e;

    // W_hh row -> registers (overlaps frame phase).
    // fold: x0.5 (sigmoid half-arg, i/f/o only) and x0.5 (hp = 2h publish).
    const float wscale = (g == 2) ? 0.5f : 0.25f;
    float w[HID];
    {
        const float4* wr = reinterpret_cast<const float4*>(whh + row * HID);
        #pragma unroll
        for (int k4 = 0; k4 < HID / 4; k4++) {
            float4 v = wr[k4];
            w[4 * k4 + 0] = v.x * wscale;
            w[4 * k4 + 1] = v.y * wscale;
            w[4 * k4 + 2] = v.z * wscale;
            w[4 * k4 + 3] = v.w * wscale;
        }
    }

    // ---- wait for the first LEAD frames (parallel flag poll) ----
    {
        int myf = 0;
        do {
            if (!myf) myf = ld_acquire_gpu(&g_flag[tid & (LEAD - 1)]);
        } while (!__syncthreads_and(myf));
        __threadfence();   // order staged-data loads after flag observation
    }
    // stage frames [0, LEAD)
    {
        #pragma unroll
        for (int f = 0; f < LEAD; f++)
            sgx[f * NG + tid] = __ldcg(&g_gx[f * NG + tid]);
    }
    __syncthreads();

    float c, hp;           // hp = 2*h (the 0.5 is folded into the weights)

    // ---- t = 0 peeled: h = 0 -> gate is just gx[0] ----
    {
        float a = tanha(sgx[row]);
        sgate[0][32 * wid + lane] = a;       // == [e*4+g], conflict-free
        __syncthreads();
        float4 gv = *reinterpret_cast<const float4*>(&sgate[0][lane * 4]); // (ti,tf,tg,to)
        c = 0.5f * fmaf(gv.x, gv.z, gv.z);   // sigma_i * tanh_g (c0 = 0)
        float th = tanha(c);
        hp = fmaf(gv.w, th, th);             // 2 * sigma_o * tanh(c)
    }

    // in-loop staging state (one frame per step, one-step-deferred STS)
    int   sp   = LEAD;
    int   have = 0;
    float dval = 0.0f;

    #pragma unroll 1
    for (int t = 1; t < T_FRAMES; t++) {
        // ---- pipelined staging (no stalls: LDG consumed one step later) ----
        if (t >= CONFIRM_T) {
            if (t == CONFIRM_T) {
                // one-time: all frames certainly done by now; acquire-read
                while (ld_acquire_gpu(&g_done) < T_FRAMES) { }
            }
            if (have) { sgx[sp * NG + tid] = dval; sp++; have = 0; }
            if (sp < T_FRAMES) { dval = __ldcg(&g_gx[sp * NG + tid]); have = 1; }
        }

        // ---- recurrence step ----
        shbuf[wid][lane] = hp;               // publish h (warp-private buffer)
        float gx0 = sgx[t * NG + row];
        __syncwarp();

        float acc[8];
        acc[0] = gx0;
        #pragma unroll
        for (int i = 1; i < 8; i++) acc[i] = 0.0f;

        #pragma unroll
        for (int k4 = 0; k4 < 8; k4++) {
            float4 hv = *reinterpret_cast<const float4*>(&shbuf[wid][k4 * 4]); // broadcast
            acc[k4] = fmaf(w[4 * k4 + 0], hv.x, acc[k4]);
            acc[k4] = fmaf(w[4 * k4 + 1], hv.y, acc[k4]);
            acc[k4] = fmaf(w[4 * k4 + 2], hv.z, acc[k4]);
            acc[k4] = fmaf(w[4 * k4 + 3], hv.w, acc[k4]);
        }
        float gs = ((acc[0] + acc[1]) + (acc[2] + acc[3]))
                 + ((acc[4] + acc[5]) + (acc[6] + acc[7]));

        float a = tanha(gs);                 // raw tanh for ALL gates

        float* buf = sgate[t & 1];
        buf[32 * wid + lane] = a;            // conflict-free transposed write
        __syncthreads();                     // one barrier per step

        float4 gv = *reinterpret_cast<const float4*>(&buf[lane * 4]); // (ti,tf,tg,to)
        // c = sigma_f*c + sigma_i*tanh_g = 0.5*((tf*c + c) + (ti*tg + tg))
        c = 0.5f * (fmaf(gv.y, c, c) + fmaf(gv.x, gv.z, gv.z));
        float th = tanha(c);
        hp = fmaf(gv.w, th, th);             // 2*h
    }

    // ---- output head ----
    float h  = 0.5f * hp;                    // undo the h-fold
    float hb = (h * rsqrtf(1.0f + EPSF)) * bng[lane] + bnb[lane];

    float o1 = b10[lane];
    #pragma unroll
    for (int k = 0; k < 32; k++)
        o1 = fmaf(w10[lane * 32 + k], __shfl_sync(FULLM, hb, k), o1);
    o1 = fmaxf(o1, 0.0f);

    float o2 = b11[lane];
    #pragma unroll
    for (int k = 0; k < 32; k++)
        o2 = fmaf(w11[lane * 32 + k], __shfl_sync(FULLM, o1, k), o2);
    o2 = fmaxf(o2, 0.0f);

    // warp w -> output rows [64w, 64w+64): 2 rows per lane
    const int r0 = wid * 64 + lane;
    const int r1 = r0 + 32;
    float a0 = b12[r0], a1 = b12[r1];
    #pragma unroll
    for (int k = 0; k < 32; k++) {
        float v = __shfl_sync(FULLM, o2, k);
        a0 = fmaf(w12[r0 * 32 + k], v, a0);
        a1 = fmaf(w12[r1 * 32 + k], v, a1);
    }
    out[r0] = a0;
    out[r1] = a1;

    // reset sync state for the next graph replay (this kernel fully consumed
    // all frames; the next launch cannot start before this one completes)
    __syncthreads();
    if (tid < T_FRAMES) g_flag[tid] = 0;
    if (tid == 0) g_done = 0;
}

// ---------------------------------------------------------------------------
// Input order (metadata): x, w00, b00, w01, b01, ln_g, ln_b, w_ih, w_hh,
//                         b_ih, b_hh, bn_g, bn_b, w10, b10, w11, b11, w12, b12
// ---------------------------------------------------------------------------
extern "C" void kernel_launch(void* const* d_in, const int* in_sizes, int n_in,
                              void* d_out, int out_size)
{
    const float* x    = (const float*)d_in[0];
    const float* w00  = (const float*)d_in[1];
    const float* b00  = (const float*)d_in[2];
    const float* w01  = (const float*)d_in[3];
    const float* b01  = (const float*)d_in[4];
    const float* lng  = (const float*)d_in[5];
    const float* lnb  = (const float*)d_in[6];
    const float* wih  = (const float*)d_in[7];
    const float* whh  = (const float*)d_in[8];
    const float* bih  = (const float*)d_in[9];
    const float* bhh  = (const float*)d_in[10];
    const float* bng  = (const float*)d_in[11];
    const float* bnb  = (const float*)d_in[12];
    const float* w10  = (const float*)d_in[13];
    const float* b10  = (const float*)d_in[14];
    const float* w11  = (const float*)d_in[15];
    const float* b11  = (const float*)d_in[16];
    const float* w12  = (const float*)d_in[17];
    const float* b12  = (const float*)d_in[18];
    float* out = (float*)d_out;

    fused_kernel<<<T_FRAMES + 1, 128>>>(
        x, w00, b00, w01, b01, lng, lnb, wih, bih, bhh,
        whh, bng, bnb, w10, b10, w11, b11, w12, b12, out);
}

// round 11
// speedup vs baseline: 1.1623x; 1.1623x over previous
#include <cuda_runtime.h>

#define T_FRAMES 60
#define HID 32
#define NG 128          // 4*HID gate rows
#define EPSF 1e-5f
#define FULLM 0xffffffffu

// per-frame gate pre-activations (i/f/o rows pre-scaled by 0.5; g rows raw)
__device__ float g_gx[T_FRAMES * NG];
__device__ int   g_done = 0;

__device__ __forceinline__ float tanha(float x) {
    float r; asm("tanh.approx.f32 %0, %1;" : "=f"(r) : "f"(x)); return r;
}

// ---------------------------------------------------------------------------
// Fused kernel: blocks 0..59 = per-frame MLP+LN+W_ih matvec (parallel),
// block 60 = recurrence + output head. One wave (61 blocks < 148 SMs).
// Seq block: loads W_hh regs during frame phase, spins on the counter, then
// bulk-stages gx into smem (ldcg) and runs the branch-free smem recurrence.
// ---------------------------------------------------------------------------
__global__ void __launch_bounds__(128, 1) fused_kernel(
    const float* __restrict__ x,
    const float* __restrict__ w00, const float* __restrict__ b00,
    const float* __restrict__ w01, const float* __restrict__ b01,
    const float* __restrict__ lng, const float* __restrict__ lnb,
    const float* __restrict__ wih, const float* __restrict__ bih,
    const float* __restrict__ bhh,
    const float* __restrict__ whh,
    const float* __restrict__ bng, const float* __restrict__ bnb,
    const float* __restrict__ w10, const float* __restrict__ b10,
    const float* __restrict__ w11, const float* __restrict__ b11,
    const float* __restrict__ w12, const float* __restrict__ b12,
    float* __restrict__ out)
{
    const int tid  = threadIdx.x;
    const int wid  = tid >> 5;
    const int lane = tid & 31;

    if (blockIdx.x < T_FRAMES) {
        // =================== frame path (parallel over t) ===================
        const int t = blockIdx.x;

        __shared__ float sx[63];
        __shared__ float sf1[63];
        __shared__ float sf2[64];
        __shared__ float sfn[64];
        __shared__ float s_mu, s_rstd;

        if (tid < 63) sx[tid] = x[t * 63 + tid];
        __syncthreads();

        if (tid < 63) {
            float acc = b00[tid];
            const float* wr = w00 + tid * 63;
            #pragma unroll
            for (int k = 0; k < 63; k++) acc = fmaf(wr[k], sx[k], acc);
            sf1[tid] = fmaxf(acc, 0.0f);
        }
        __syncthreads();

        if (tid < 64) {
            float acc = b01[tid];
            const float* wr = w01 + tid * 63;
            #pragma unroll
            for (int k = 0; k < 63; k++) acc = fmaf(wr[k], sf1[k], acc);
            sf2[tid] = fmaxf(acc, 0.0f);
        }
        __syncthreads();

        if (tid < 32) {
            float v0 = sf2[tid], v1 = sf2[tid + 32];
            float s = v0 + v1;
            float q = v0 * v0 + v1 * v1;
            #pragma unroll
            for (int o = 16; o > 0; o >>= 1) {
                s += __shfl_xor_sync(FULLM, s, o);
                q += __shfl_xor_sync(FULLM, q, o);
            }
            if (tid == 0) {
                float mu  = s * (1.0f / 64.0f);
                float var = q * (1.0f / 64.0f) - mu * mu;
                s_mu   = mu;
                s_rstd = rsqrtf(var + EPSF);
            }
        }
        __syncthreads();

        if (tid < 64)
            sfn[tid] = (sf2[tid] - s_mu) * s_rstd * lng[tid] + lnb[tid];
        __syncthreads();

        {
            float acc = bih[tid] + bhh[tid];
            const float* wr = wih + tid * 64;
            #pragma unroll
            for (int k = 0; k < 64; k++) acc = fmaf(wr[k], sfn[k], acc);
            // g gate rows (64..95) raw; i/f/o rows scaled by 0.5 (sigmoid arg)
            float scale = ((tid >> 5) == 2) ? 1.0f : 0.5f;
            g_gx[t * NG + tid] = acc * scale;
        }
        __syncthreads();
        if (tid == 0) {
            __threadfence();
            atomicAdd(&g_done, 1);
        }
        return;
    }

    // ======================= sequential path (block 60) =====================
    // lane mapping: element e = 8*wid + (lane>>2), gate g = lane&3,
    // gate row = 32*g + e  (rows: i 0-31, f 32-63, g 64-95, o 96-127).
    __shared__ float sgx[T_FRAMES * NG];              // 30 KB staged gx
    __shared__ __align__(16) float sgate[2][NG];      // [elem*4 + gate]
    __shared__ __align__(16) float shbuf[4][HID];     // per-warp private h copy

    const int g   = lane & 3;
    const int e   = 8 * wid + (lane >> 2);
    const int row = 32 * g + e;

    // W_hh row -> registers (overlaps frame phase).
    // fold: x0.5 sigmoid half-arg (i/f/o only) and x0.5 for hp = 2h publish.
    const float wscale = (g == 2) ? 0.5f : 0.25f;
    float w[HID];
    {
        const float4* wr = reinterpret_cast<const float4*>(whh + row * HID);
        #pragma unroll
        for (int k4 = 0; k4 < HID / 4; k4++) {
            float4 v = wr[k4];
            w[4 * k4 + 0] = v.x * wscale;
            w[4 * k4 + 1] = v.y * wscale;
            w[4 * k4 + 2] = v.z * wscale;
            w[4 * k4 + 3] = v.w * wscale;
        }
    }

    // wait for all frame blocks
    if (tid == 0) {
        volatile int* p = &g_done;
        while (*p < T_FRAMES) { }
        __threadfence();
    }
    __syncthreads();

    // bulk-stage gx into smem (L2 -> smem, MLP-rich)
    {
        float4* s4 = reinterpret_cast<float4*>(sgx);
        const float4* g4 = reinterpret_cast<const float4*>(g_gx);
        #pragma unroll
        for (int i = tid; i < (T_FRAMES * NG) / 4; i += 128)
            s4[i] = __ldcg(g4 + i);
    }
    __syncthreads();

    float c, hp;           // hp = 2*h (the 0.5 is folded into the weights)

    // ---- t = 0 peeled: h = 0 -> gate is just gx[0] ----
    {
        float a = tanha(sgx[row]);
        sgate[0][32 * wid + lane] = a;       // == [e*4+g], conflict-free
        __syncthreads();
        float4 gv = *reinterpret_cast<const float4*>(&sgate[0][lane * 4]); // (ti,tf,tg,to)
        c = 0.5f * fmaf(gv.x, gv.z, gv.z);   // sigma_i * tanh_g (c0 = 0)
        float th = tanha(c);
        hp = fmaf(gv.w, th, th);             // 2 * sigma_o * tanh(c)
    }

    #pragma unroll 1
    for (int t = 1; t < T_FRAMES; t++) {
        shbuf[wid][lane] = hp;               // publish 2h (warp-private buffer)
        float gx0 = sgx[t * NG + row];
        __syncwarp();

        float acc[8];
        acc[0] = gx0;
        #pragma unroll
        for (int i = 1; i < 8; i++) acc[i] = 0.0f;

        #pragma unroll
        for (int k4 = 0; k4 < 8; k4++) {
            float4 hv = *reinterpret_cast<const float4*>(&shbuf[wid][k4 * 4]); // broadcast
            acc[k4] = fmaf(w[4 * k4 + 0], hv.x, acc[k4]);
            acc[k4] = fmaf(w[4 * k4 + 1], hv.y, acc[k4]);
            acc[k4] = fmaf(w[4 * k4 + 2], hv.z, acc[k4]);
            acc[k4] = fmaf(w[4 * k4 + 3], hv.w, acc[k4]);
        }
        float gs = ((acc[0] + acc[1]) + (acc[2] + acc[3]))
                 + ((acc[4] + acc[5]) + (acc[6] + acc[7]));

        float a = tanha(gs);                 // raw tanh for ALL gates

        float* buf = sgate[t & 1];
        buf[32 * wid + lane] = a;            // conflict-free transposed write
        __syncthreads();                     // one barrier per step

        float4 gv = *reinterpret_cast<const float4*>(&buf[lane * 4]); // (ti,tf,tg,to)
        // c = sigma_f*c + sigma_i*tanh_g = 0.5*((tf*c + c) + (ti*tg + tg))
        c = 0.5f * (fmaf(gv.y, c, c) + fmaf(gv.x, gv.z, gv.z));
        float th = tanha(c);
        hp = fmaf(gv.w, th, th);             // 2*h
    }

    // ---- output head ----
    float h  = 0.5f * hp;                    // undo the h-fold
    float hb = (h * rsqrtf(1.0f + EPSF)) * bng[lane] + bnb[lane];

    float o1 = b10[lane];
    #pragma unroll
    for (int k = 0; k < 32; k++)
        o1 = fmaf(w10[lane * 32 + k], __shfl_sync(FULLM, hb, k), o1);
    o1 = fmaxf(o1, 0.0f);

    float o2 = b11[lane];
    #pragma unroll
    for (int k = 0; k < 32; k++)
        o2 = fmaf(w11[lane * 32 + k], __shfl_sync(FULLM, o1, k), o2);
    o2 = fmaxf(o2, 0.0f);

    // warp w -> output rows [64w, 64w+64): 2 rows per lane
    const int r0 = wid * 64 + lane;
    const int r1 = r0 + 32;
    float a0 = b12[r0], a1 = b12[r1];
    #pragma unroll
    for (int k = 0; k < 32; k++) {
        float v = __shfl_sync(FULLM, o2, k);
        a0 = fmaf(w12[r0 * 32 + k], v, a0);
        a1 = fmaf(w12[r1 * 32 + k], v, a1);
    }
    out[r0] = a0;
    out[r1] = a1;

    // reset counter for next replay (all producers already finished; the next
    // launch cannot begin before this kernel completes)
    __syncthreads();
    if (tid == 0) g_done = 0;
}

// ---------------------------------------------------------------------------
// Input order (metadata): x, w00, b00, w01, b01, ln_g, ln_b, w_ih, w_hh,
//                         b_ih, b_hh, bn_g, bn_b, w10, b10, w11, b11, w12, b12
// ---------------------------------------------------------------------------
extern "C" void kernel_launch(void* const* d_in, const int* in_sizes, int n_in,
                              void* d_out, int out_size)
{
    const float* x    = (const float*)d_in[0];
    const float* w00  = (const float*)d_in[1];
    const float* b00  = (const float*)d_in[2];
    const float* w01  = (const float*)d_in[3];
    const float* b01  = (const float*)d_in[4];
    const float* lng  = (const float*)d_in[5];
    const float* lnb  = (const float*)d_in[6];
    const float* wih  = (const float*)d_in[7];
    const float* whh  = (const float*)d_in[8];
    const float* bih  = (const float*)d_in[9];
    const float* bhh  = (const float*)d_in[10];
    const float* bng  = (const float*)d_in[11];
    const float* bnb  = (const float*)d_in[12];
    const float* w10  = (const float*)d_in[13];
    const float* b10  = (const float*)d_in[14];
    const float* w11  = (const float*)d_in[15];
    const float* b11  = (const float*)d_in[16];
    const float* w12  = (const float*)d_in[17];
    const float* b12  = (const float*)d_in[18];
    float* out = (float*)d_out;

    fused_kernel<<<T_FRAMES + 1, 128>>>(
        x, w00, b00, w01, b01, lng, lnb, wih, bih, bhh,
        whh, bng, bnb, w10, b10, w11, b11, w12, b12, out);
}